// round 1
// baseline (speedup 1.0000x reference)
#include <cuda_runtime.h>

#define NCH    128
#define NGROUP 32
#define CPG    4
#define NB     16
#define EPS    1e-5f
#define RPB    1024   // rows per reduce block

// scratch: per batch, [0..127] = per-channel sum, [128..255] = per-channel sumsq
__device__ float g_sums[NB * 256];
__device__ float g_A[NB * NCH];   // inv_std * weight
__device__ float g_Bp[NB * NCH];  // bias - mean * inv_std * weight

__global__ void zero_kernel() {
    int i = blockIdx.x * blockDim.x + threadIdx.x;
    if (i < NB * 256) g_sums[i] = 0.0f;
}

__global__ __launch_bounds__(256) void reduce_kernel(
    const float4* __restrict__ data4,
    const int* __restrict__ bid, int n)
{
    const int lane = threadIdx.x & 31;   // float4 column -> group id
    const int rg   = threadIdx.x >> 5;   // 0..7 row group
    const int blockStart = blockIdx.x * RPB;
    const int rowEnd = min(n, blockStart + RPB);

    float4 s = make_float4(0.f, 0.f, 0.f, 0.f);
    float4 q = make_float4(0.f, 0.f, 0.f, 0.f);
    int cur_b = -1;

    for (int row = blockStart + rg; row < rowEnd; row += 8) {
        int b = __ldg(bid + row);
        if (b != cur_b) {
            if (cur_b >= 0) {   // rare: batch boundary inside this block
                int base = cur_b * 256 + lane * 4;
                atomicAdd(&g_sums[base + 0], s.x);
                atomicAdd(&g_sums[base + 1], s.y);
                atomicAdd(&g_sums[base + 2], s.z);
                atomicAdd(&g_sums[base + 3], s.w);
                atomicAdd(&g_sums[base + 128 + 0], q.x);
                atomicAdd(&g_sums[base + 128 + 1], q.y);
                atomicAdd(&g_sums[base + 128 + 2], q.z);
                atomicAdd(&g_sums[base + 128 + 3], q.w);
                s = make_float4(0.f, 0.f, 0.f, 0.f);
                q = make_float4(0.f, 0.f, 0.f, 0.f);
            }
            cur_b = b;
        }
        float4 v = __ldg(data4 + row * 32 + lane);
        s.x += v.x; s.y += v.y; s.z += v.z; s.w += v.w;
        q.x = fmaf(v.x, v.x, q.x);
        q.y = fmaf(v.y, v.y, q.y);
        q.z = fmaf(v.z, v.z, q.z);
        q.w = fmaf(v.w, v.w, q.w);
    }

    __shared__ float sh[8][256];
    __shared__ int flag;
    if (threadIdx.x == 0) flag = 0;
    __syncthreads();

    const int b_ref = __ldg(bid + blockStart);   // blockStart < n by construction
    if (cur_b >= 0 && cur_b != b_ref) flag = 1;  // benign race
    __syncthreads();

    if (flag) {
        // mixed-final block (at most a handful per launch): direct atomics
        if (cur_b >= 0) {
            int base = cur_b * 256 + lane * 4;
            atomicAdd(&g_sums[base + 0], s.x);
            atomicAdd(&g_sums[base + 1], s.y);
            atomicAdd(&g_sums[base + 2], s.z);
            atomicAdd(&g_sums[base + 3], s.w);
            atomicAdd(&g_sums[base + 128 + 0], q.x);
            atomicAdd(&g_sums[base + 128 + 1], q.y);
            atomicAdd(&g_sums[base + 128 + 2], q.z);
            atomicAdd(&g_sums[base + 128 + 3], q.w);
        }
    } else {
        // fast path: all accumulators belong to b_ref (tail threads hold zeros)
        int base = lane * 4;
        sh[rg][base + 0] = s.x;
        sh[rg][base + 1] = s.y;
        sh[rg][base + 2] = s.z;
        sh[rg][base + 3] = s.w;
        sh[rg][128 + base + 0] = q.x;
        sh[rg][128 + base + 1] = q.y;
        sh[rg][128 + base + 2] = q.z;
        sh[rg][128 + base + 3] = q.w;
        __syncthreads();
        float tot = 0.f;
        #pragma unroll
        for (int r = 0; r < 8; r++) tot += sh[r][threadIdx.x];
        atomicAdd(&g_sums[b_ref * 256 + threadIdx.x], tot);
    }
}

__global__ __launch_bounds__(512) void stats_kernel(
    const int* __restrict__ bid, int n,
    const float* __restrict__ w, const float* __restrict__ bias)
{
    __shared__ int start[NB + 1];
    const int tid = threadIdx.x;
    if (tid <= NB) {
        if (tid == 0)       start[0]  = 0;
        else if (tid == NB) start[NB] = n;
        else {
            int lo = 0, hi = n;            // lower_bound(batch_id, tid)
            while (lo < hi) {
                int mid = (lo + hi) >> 1;
                if (__ldg(bid + mid) < tid) lo = mid + 1; else hi = mid;
            }
            start[tid] = lo;
        }
    }
    __syncthreads();

    if (tid < NB * NGROUP) {
        const int b = tid >> 5, g = tid & 31;
        const float nb    = (float)(start[b + 1] - start[b]);
        const float count = nb * (float)CPG;
        const float inv   = 1.0f / (count + EPS);

        const float* sp = &g_sums[b * 256 + g * 4];
        const float* qp = sp + 128;
        float S  = sp[0] + sp[1] + sp[2] + sp[3];
        float SS = qp[0] + qp[1] + qp[2] + qp[3];

        float m    = S * inv;
        float var  = inv * (SS - 2.0f * m * S + count * m * m);
        float istd = rsqrtf(var + EPS);

        #pragma unroll
        for (int k = 0; k < 4; k++) {
            int c = g * 4 + k;
            float a = istd * __ldg(w + c);
            g_A[b * NCH + c]  = a;
            g_Bp[b * NCH + c] = __ldg(bias + c) - m * a;
        }
    }
}

__global__ __launch_bounds__(256) void norm_kernel(
    const float4* __restrict__ data4,
    const int* __restrict__ bid,
    float4* __restrict__ out4, int n)
{
    int i = blockIdx.x * blockDim.x + threadIdx.x;
    if (i >= n * 32) return;
    int row  = i >> 5;
    int lane = i & 31;
    int b    = __ldg(bid + row);

    float4 v = __ldg(data4 + i);
    const float4* A4 = (const float4*)g_A;
    const float4* B4 = (const float4*)g_Bp;
    float4 a = __ldg(A4 + b * 32 + lane);
    float4 c = __ldg(B4 + b * 32 + lane);

    float4 o;
    o.x = fmaf(v.x, a.x, c.x);
    o.y = fmaf(v.y, a.y, c.y);
    o.z = fmaf(v.z, a.z, c.z);
    o.w = fmaf(v.w, a.w, c.w);
    out4[i] = o;
}

extern "C" void kernel_launch(void* const* d_in, const int* in_sizes, int n_in,
                              void* d_out, int out_size)
{
    const float* data    = (const float*)d_in[0];
    const float* weights = (const float*)d_in[1];
    const float* bias    = (const float*)d_in[2];
    const int*   bid     = (const int*)d_in[3];
    const int    n       = in_sizes[3];          // number of rows

    const float4* data4 = (const float4*)data;
    float4*       out4  = (float4*)d_out;

    zero_kernel<<<16, 256>>>();
    reduce_kernel<<<(n + RPB - 1) / RPB, 256>>>(data4, bid, n);
    stats_kernel<<<1, 512>>>(bid, n, weights, bias);
    int total4 = n * 32;
    norm_kernel<<<(total4 + 255) / 256, 256>>>(data4, bid, out4, n);
}

// round 5
// speedup vs baseline: 1.1372x; 1.1372x over previous
#include <cuda_runtime.h>

#define NCH    128
#define NGROUP 32
#define CPG    4
#define NB     16
#define EPS    1e-5f
#define RPB    1024   // rows per reduce block
#define NITER  8      // float4 per thread in norm

// scratch
__device__ float g_sums[NB * 256];   // per batch: [0..127] sum, [128..255] sumsq
__device__ float g_A[NB * NCH];      // inv_std * weight
__device__ float g_Bp[NB * NCH];     // bias - mean * inv_std * weight
__device__ int   g_start[NB + 1];    // segment boundaries (batch_id sorted)

__device__ __forceinline__ int segof(int row, const int* __restrict__ ss) {
    int b = 0;
    #pragma unroll
    for (int k = 1; k < NB; k++) b += (row >= ss[k]);
    return b;
}

// ── 1. boundaries (binary search on sorted batch_id) + zero scratch ──────────
__global__ __launch_bounds__(256) void bounds_kernel(const int* __restrict__ bid, int n) {
    const int tid = threadIdx.x;
    if (tid <= NB) {
        if (tid == 0)       g_start[0]  = 0;
        else if (tid == NB) g_start[NB] = n;
        else {
            int lo = 0, hi = n;
            while (lo < hi) {
                int mid = (lo + hi) >> 1;
                if (__ldg(bid + mid) < tid) lo = mid + 1; else hi = mid;
            }
            g_start[tid] = lo;
        }
    }
    for (int i = tid; i < NB * 256; i += 256) g_sums[i] = 0.0f;
}

// ── 2. reduce: per-(batch,channel) sum + sumsq, no bid loads ─────────────────
__global__ __launch_bounds__(256) void reduce_kernel(const float4* __restrict__ data4, int n)
{
    __shared__ int   ss[NB + 1];
    __shared__ float sh[8][256];
    if (threadIdx.x <= NB) ss[threadIdx.x] = g_start[threadIdx.x];
    __syncthreads();

    const int lane = threadIdx.x & 31;   // float4 column == group id
    const int rg   = threadIdx.x >> 5;
    const int blockStart = blockIdx.x * RPB;
    const int rowEnd = min(n, blockStart + RPB);

    const int b0 = segof(blockStart, ss);
    const int b1 = segof(rowEnd - 1, ss);

    float4 s = make_float4(0.f, 0.f, 0.f, 0.f);
    float4 q = make_float4(0.f, 0.f, 0.f, 0.f);

    if (b0 == b1) {
        // fast path: whole block in one segment — branch-free streaming
        #pragma unroll 4
        for (int row = blockStart + rg; row < rowEnd; row += 8) {
            float4 v = __ldcs(data4 + (size_t)row * 32 + lane);
            s.x += v.x; s.y += v.y; s.z += v.z; s.w += v.w;
            q.x = fmaf(v.x, v.x, q.x);
            q.y = fmaf(v.y, v.y, q.y);
            q.z = fmaf(v.z, v.z, q.z);
            q.w = fmaf(v.w, v.w, q.w);
        }
        int base = lane * 4;
        sh[rg][base + 0] = s.x;  sh[rg][base + 1] = s.y;
        sh[rg][base + 2] = s.z;  sh[rg][base + 3] = s.w;
        sh[rg][128 + base + 0] = q.x;  sh[rg][128 + base + 1] = q.y;
        sh[rg][128 + base + 2] = q.z;  sh[rg][128 + base + 3] = q.w;
        __syncthreads();
        float tot = 0.f;
        #pragma unroll
        for (int r = 0; r < 8; r++) tot += sh[r][threadIdx.x];
        atomicAdd(&g_sums[b0 * 256 + threadIdx.x], tot);
    } else {
        // rare: block spans a segment boundary (≤ B-1 blocks total)
        int cur_b = -1;
        for (int row = blockStart + rg; row < rowEnd; row += 8) {
            int b = segof(row, ss);
            if (b != cur_b) {
                if (cur_b >= 0) {
                    int base = cur_b * 256 + lane * 4;
                    atomicAdd(&g_sums[base + 0], s.x);
                    atomicAdd(&g_sums[base + 1], s.y);
                    atomicAdd(&g_sums[base + 2], s.z);
                    atomicAdd(&g_sums[base + 3], s.w);
                    atomicAdd(&g_sums[base + 128 + 0], q.x);
                    atomicAdd(&g_sums[base + 128 + 1], q.y);
                    atomicAdd(&g_sums[base + 128 + 2], q.z);
                    atomicAdd(&g_sums[base + 128 + 3], q.w);
                    s = make_float4(0.f, 0.f, 0.f, 0.f);
                    q = make_float4(0.f, 0.f, 0.f, 0.f);
                }
                cur_b = b;
            }
            float4 v = __ldcs(data4 + (size_t)row * 32 + lane);
            s.x += v.x; s.y += v.y; s.z += v.z; s.w += v.w;
            q.x = fmaf(v.x, v.x, q.x);
            q.y = fmaf(v.y, v.y, q.y);
            q.z = fmaf(v.z, v.z, q.z);
            q.w = fmaf(v.w, v.w, q.w);
        }
        if (cur_b >= 0) {
            int base = cur_b * 256 + lane * 4;
            atomicAdd(&g_sums[base + 0], s.x);
            atomicAdd(&g_sums[base + 1], s.y);
            atomicAdd(&g_sums[base + 2], s.z);
            atomicAdd(&g_sums[base + 3], s.w);
            atomicAdd(&g_sums[base + 128 + 0], q.x);
            atomicAdd(&g_sums[base + 128 + 1], q.y);
            atomicAdd(&g_sums[base + 128 + 2], q.z);
            atomicAdd(&g_sums[base + 128 + 3], q.w);
        }
    }
}

// ── 3. fold stats into per-(batch,channel) affine coefficients ───────────────
__global__ __launch_bounds__(512) void stats_kernel(
    const float* __restrict__ w, const float* __restrict__ bias)
{
    const int tid = threadIdx.x;
    if (tid < NB * NGROUP) {
        const int b = tid >> 5, g = tid & 31;
        const float nb    = (float)(g_start[b + 1] - g_start[b]);
        const float count = nb * (float)CPG;
        const float inv   = 1.0f / (count + EPS);

        const float* sp = &g_sums[b * 256 + g * 4];
        const float* qp = sp + 128;
        float S  = sp[0] + sp[1] + sp[2] + sp[3];
        float SS = qp[0] + qp[1] + qp[2] + qp[3];

        float m    = S * inv;
        float var  = inv * (SS - 2.0f * m * S + count * m * m);
        float istd = rsqrtf(var + EPS);

        #pragma unroll
        for (int k = 0; k < 4; k++) {
            int c = g * 4 + k;
            float a = istd * __ldg(w + c);
            g_A[b * NCH + c]  = a;
            g_Bp[b * NCH + c] = __ldg(bias + c) - m * a;
        }
    }
}

// ── 4. normalize: out = x*A + B, pure streaming, MLP=8 per thread ────────────
__global__ __launch_bounds__(256) void norm_kernel(
    const float4* __restrict__ data4, float4* __restrict__ out4, int n4, int n)
{
    __shared__ int ss[NB + 1];
    if (threadIdx.x <= NB) ss[threadIdx.x] = g_start[threadIdx.x];
    __syncthreads();

    const int base = blockIdx.x * (256 * NITER) + threadIdx.x;
    const int firstRow = (blockIdx.x * (256 * NITER)) >> 5;
    const int lastRow  = min(n - 1, ((blockIdx.x + 1) * (256 * NITER) - 1) >> 5);
    const int b0 = segof(firstRow, ss);
    const int b1 = segof(lastRow, ss);

    const float4* A4 = (const float4*)g_A;
    const float4* B4 = (const float4*)g_Bp;

    if (b0 == b1) {
        // fast path: whole block one segment; lane invariant across k (256%32==0)
        const int lane = threadIdx.x & 31;
        const float4 a = __ldg(A4 + b0 * 32 + lane);
        const float4 c = __ldg(B4 + b0 * 32 + lane);

        float4 v[NITER];
        #pragma unroll
        for (int k = 0; k < NITER; k++) {
            int i = base + k * 256;
            if (i < n4) v[k] = __ldcs(data4 + i);
        }
        #pragma unroll
        for (int k = 0; k < NITER; k++) {
            int i = base + k * 256;
            if (i < n4) {
                float4 o;
                o.x = fmaf(v[k].x, a.x, c.x);
                o.y = fmaf(v[k].y, a.y, c.y);
                o.z = fmaf(v[k].z, a.z, c.z);
                o.w = fmaf(v[k].w, a.w, c.w);
                __stcs(out4 + i, o);
            }
        }
    } else {
        // rare boundary block
        const int lane = threadIdx.x & 31;
        #pragma unroll
        for (int k = 0; k < NITER; k++) {
            int i = base + k * 256;
            if (i < n4) {
                int row = i >> 5;
                int b = segof(row, ss);
                float4 a = __ldg(A4 + b * 32 + lane);
                float4 c = __ldg(B4 + b * 32 + lane);
                float4 v = __ldcs(data4 + i);
                float4 o;
                o.x = fmaf(v.x, a.x, c.x);
                o.y = fmaf(v.y, a.y, c.y);
                o.z = fmaf(v.z, a.z, c.z);
                o.w = fmaf(v.w, a.w, c.w);
                __stcs(out4 + i, o);
            }
        }
    }
}

extern "C" void kernel_launch(void* const* d_in, const int* in_sizes, int n_in,
                              void* d_out, int out_size)
{
    const float* data    = (const float*)d_in[0];
    const float* weights = (const float*)d_in[1];
    const float* bias    = (const float*)d_in[2];
    const int*   bid     = (const int*)d_in[3];
    const int    n       = in_sizes[3];

    const float4* data4 = (const float4*)data;
    float4*       out4  = (float4*)d_out;
    const int n4 = n * 32;

    bounds_kernel<<<1, 256>>>(bid, n);
    reduce_kernel<<<(n + RPB - 1) / RPB, 256>>>(data4, n);
    stats_kernel<<<1, 512>>>(weights, bias);
    norm_kernel<<<(n4 + 256 * NITER - 1) / (256 * NITER), 256>>>(data4, out4, n4, n);
}